// round 2
// baseline (speedup 1.0000x reference)
#include <cuda_runtime.h>

#define SEQ   2048
#define HIDN  2048
#define NH    16
#define HD    128
#define NBLK  32
#define BLK   64
#define KSEL  8

// ---- scratch (device globals: no allocation allowed) ----
__device__ float    g_q[SEQ * HIDN];
__device__ float    g_k[SEQ * HIDN];
__device__ float    g_v[SEQ * HIDN];
__device__ float    g_kg[NBLK * HIDN];
__device__ unsigned g_sel[NH * SEQ];
__device__ float    g_o[SEQ * HIDN];

__device__ __forceinline__ float finf() { return __int_as_float(0x7f800000); }

// ============================================================
// SGEMM: C[2048x2048] = A[2048x2048] @ B[2048x2048], row-major.
// 128x128 tile, BK=8, 256 threads, 8x8 microtile.
// ============================================================
__device__ __forceinline__ void sgemm_body(const float* __restrict__ A,
                                           const float* __restrict__ B,
                                           float* __restrict__ C) {
    __shared__ float As[8 * 128];   // [k][m] (transposed)
    __shared__ float Bs[8 * 128];   // [k][n]

    const int tid  = threadIdx.x;
    const int cRow = blockIdx.y * 128;
    const int cCol = blockIdx.x * 128;
    const int tRow = (tid >> 4) * 8;      // 0..120
    const int tCol = (tid & 15) * 8;      // 0..120
    const int aRow = tid >> 1;            // 0..127
    const int aCol = (tid & 1) << 2;      // 0 or 4
    const int bRow = tid >> 5;            // 0..7
    const int bCol = (tid & 31) << 2;     // 0..124

    float acc[8][8];
#pragma unroll
    for (int i = 0; i < 8; i++)
#pragma unroll
        for (int j = 0; j < 8; j++) acc[i][j] = 0.f;

    float rM[8], rN[8];

    for (int k0 = 0; k0 < HIDN; k0 += 8) {
        float4 a4 = *(const float4*)(A + (size_t)(cRow + aRow) * HIDN + k0 + aCol);
        As[(aCol + 0) * 128 + aRow] = a4.x;
        As[(aCol + 1) * 128 + aRow] = a4.y;
        As[(aCol + 2) * 128 + aRow] = a4.z;
        As[(aCol + 3) * 128 + aRow] = a4.w;
        *(float4*)(Bs + bRow * 128 + bCol) =
            *(const float4*)(B + (size_t)(k0 + bRow) * HIDN + cCol + bCol);
        __syncthreads();
#pragma unroll
        for (int kk = 0; kk < 8; kk++) {
#pragma unroll
            for (int i = 0; i < 8; i++) rM[i] = As[kk * 128 + tRow + i];
#pragma unroll
            for (int j = 0; j < 8; j++) rN[j] = Bs[kk * 128 + tCol + j];
#pragma unroll
            for (int i = 0; i < 8; i++)
#pragma unroll
                for (int j = 0; j < 8; j++) acc[i][j] += rM[i] * rN[j];
        }
        __syncthreads();
    }

    float* Cp = C + (size_t)cRow * HIDN + cCol;
#pragma unroll
    for (int i = 0; i < 8; i++)
#pragma unroll
        for (int j = 0; j < 8; j += 4) {
            float4 c4 = make_float4(acc[i][j], acc[i][j + 1], acc[i][j + 2], acc[i][j + 3]);
            *(float4*)(Cp + (size_t)(tRow + i) * HIDN + tCol + j) = c4;
        }
}

// QKV fused: blockIdx.z selects which projection.
__global__ __launch_bounds__(256, 2) void sgemm_qkv_kernel(const float* __restrict__ hs,
                                                           const float* __restrict__ Wq,
                                                           const float* __restrict__ Wk,
                                                           const float* __restrict__ Wv) {
    const float* W;
    float* C;
    if (blockIdx.z == 0)      { W = Wq; C = g_q; }
    else if (blockIdx.z == 1) { W = Wk; C = g_k; }
    else                      { W = Wv; C = g_v; }
    sgemm_body(hs, W, C);
}

__global__ __launch_bounds__(256, 2) void sgemm_out_kernel(const float* __restrict__ Wo,
                                                           float* __restrict__ out) {
    sgemm_body(g_o, Wo, out);
}

// ============================================================
// kg[n][c] = mean over 64 rows of k
// ============================================================
__global__ void kgmean_kernel() {
    const int n = blockIdx.x;
    for (int c = threadIdx.x; c < HIDN; c += blockDim.x) {
        float sum = 0.f;
#pragma unroll
        for (int t = 0; t < BLK; t++)
            sum += g_k[(size_t)(n * BLK + t) * HIDN + c];
        g_kg[n * HIDN + c] = sum * (1.0f / 64.0f);
    }
}

// ============================================================
// Gate + top-8 selection. Block = (h, 32 query rows), 8 warps,
// each warp handles 4 rows; lane = candidate block index (nb==32).
// Selected set stored as 32-bit mask; -inf picks (future blocks) dropped.
// ============================================================
__global__ __launch_bounds__(256) void gate_topk_kernel() {
    __shared__ float kgs[NBLK * 129];
    const int h  = blockIdx.y;
    const int s0 = blockIdx.x * 32;
    const int tid = threadIdx.x;

    for (int i = tid; i < NBLK * HD; i += 256) {
        int n = i >> 7, d = i & 127;
        kgs[n * 129 + d] = g_kg[n * HIDN + h * HD + d];
    }
    __syncthreads();

    const int warp = tid >> 5, lane = tid & 31;
    for (int r = 0; r < 4; r++) {
        const int s = s0 + warp * 4 + r;
        const float* qrow = g_q + (size_t)s * HIDN + h * HD;
        float g = 0.f;
#pragma unroll 8
        for (int d = 0; d < HD; d++)
            g += __ldg(qrow + d) * kgs[lane * 129 + d];

        const int qb = s >> 6;
        if (lane == qb)      g =  finf();
        else if (lane > qb)  g = -finf();

        unsigned mask = 0;
        float work = g;
#pragma unroll
        for (int it = 0; it < KSEL; it++) {
            float v = work; int idx = lane;
#pragma unroll
            for (int off = 16; off; off >>= 1) {
                float ov = __shfl_xor_sync(0xffffffffu, v, off);
                int   oi = __shfl_xor_sync(0xffffffffu, idx, off);
                if (ov > v || (ov == v && oi < idx)) { v = ov; idx = oi; }
            }
            if (v > -finf()) mask |= (1u << idx);
            if (lane == idx) work = -finf();
        }
        if (lane == 0) g_sel[h * SEQ + s] = mask;
    }
}

// ============================================================
// Block-sparse causal attention, one CTA (128 threads) per (h, s).
// Online softmax across selected key blocks; k/v tiles in smem with
// stride-129 padding for conflict-free access.
// ============================================================
__global__ __launch_bounds__(128) void attn_kernel() {
    __shared__ float kb[BLK * 129];
    __shared__ float qs[HD];
    __shared__ float sc[BLK];
    __shared__ float red[2];

    const int h   = blockIdx.x >> 11;
    const int s   = blockIdx.x & (SEQ - 1);
    const int tid = threadIdx.x;

    qs[tid] = g_q[(size_t)s * HIDN + h * HD + tid];
    unsigned mask = g_sel[h * SEQ + s];
    const float sm_scale = 0.08838834764831845f;  // 1/sqrt(128)

    float m = -finf(), l = 0.f, acc = 0.f;
    __syncthreads();

    while (mask) {
        const int n = __ffs(mask) - 1;
        mask &= mask - 1;

        // load K block (coalesced rows, transposed-ish via padded stride)
        const float* kbase = g_k + (size_t)(n * BLK) * HIDN + h * HD + tid;
#pragma unroll 8
        for (int t = 0; t < BLK; t++)
            kb[t * 129 + tid] = kbase[(size_t)t * HIDN];
        __syncthreads();

        // scores
        if (tid < BLK) {
            const int kp = n * BLK + tid;
            if (kp <= s) {
                float d0 = 0.f;
#pragma unroll 8
                for (int d = 0; d < HD; d++)
                    d0 += qs[d] * kb[tid * 129 + d];
                sc[tid] = d0 * sm_scale;
            } else {
                sc[tid] = -finf();
            }
        }
        __syncthreads();

        // block max
        if (tid < 32) {
            float a = fmaxf(sc[tid], sc[tid + 32]);
#pragma unroll
            for (int off = 16; off; off >>= 1)
                a = fmaxf(a, __shfl_xor_sync(0xffffffffu, a, off));
            if (tid == 0) red[0] = a;
        }
        __syncthreads();

        const float newm  = fmaxf(m, red[0]);       // finite: every selected block has a causal key
        const float alpha = expf(m - newm);          // m=-inf -> 0
        if (tid < BLK) sc[tid] = expf(sc[tid] - newm);
        __syncthreads();

        // block sum of p
        if (tid < 32) {
            float a = sc[tid] + sc[tid + 32];
#pragma unroll
            for (int off = 16; off; off >>= 1)
                a += __shfl_xor_sync(0xffffffffu, a, off);
            if (tid == 0) red[1] = a;
        }
        __syncthreads();

        l = l * alpha + red[1];
        m = newm;

        // load V block into same buffer
        const float* vbase = g_v + (size_t)(n * BLK) * HIDN + h * HD + tid;
#pragma unroll 8
        for (int t = 0; t < BLK; t++)
            kb[t * 129 + tid] = vbase[(size_t)t * HIDN];
        __syncthreads();

        acc *= alpha;
#pragma unroll 16
        for (int t = 0; t < BLK; t++)
            acc += sc[t] * kb[t * 129 + tid];
        __syncthreads();   // protect kb/sc before next iteration
    }

    g_o[(size_t)s * HIDN + h * HD + tid] = acc / l;
}

// ============================================================
extern "C" void kernel_launch(void* const* d_in, const int* in_sizes, int n_in,
                              void* d_out, int out_size) {
    const float* hs = (const float*)d_in[0];
    const float* Wq = (const float*)d_in[1];
    const float* Wk = (const float*)d_in[2];
    const float* Wv = (const float*)d_in[3];
    const float* Wo = (const float*)d_in[4];
    float* out = (float*)d_out;

    dim3 gq(HIDN / 128, SEQ / 128, 3);
    sgemm_qkv_kernel<<<gq, 256>>>(hs, Wq, Wk, Wv);

    kgmean_kernel<<<NBLK, 256>>>();

    dim3 gg(SEQ / 32, NH);
    gate_topk_kernel<<<gg, 256>>>();

    attn_kernel<<<NH * SEQ, 128>>>();

    dim3 go(HIDN / 128, SEQ / 128);
    sgemm_out_kernel<<<go, 256>>>(Wo, out);
}

// round 7
// speedup vs baseline: 1.3412x; 1.3412x over previous
#include <cuda_runtime.h>
#include <cuda_bf16.h>

typedef unsigned short u16;
typedef unsigned int   u32;

#define SEQ   2048
#define HIDN  2048
#define NH    16
#define HD    128
#define NBLK  32
#define BLK   64
#define KSEL  8
#define SSTR  40   // smem row stride in bf16 units (32 data + 8 pad)

__device__ float    g_q[SEQ * HIDN];
__device__ float    g_k[SEQ * HIDN];
__device__ float    g_v[SEQ * HIDN];
__device__ float    g_kg[NBLK * HIDN];
__device__ unsigned g_sel[NH * SEQ];
__device__ float    g_o[SEQ * HIDN];
__device__ u16 g_hsHi[SEQ * HIDN];
__device__ u16 g_hsLo[SEQ * HIDN];
__device__ u16 g_WTHi[4][HIDN * HIDN];
__device__ u16 g_WTLo[4][HIDN * HIDN];
__device__ u16 g_oHi[SEQ * HIDN];
__device__ u16 g_oLo[SEQ * HIDN];

__device__ __forceinline__ float finf() { return __int_as_float(0x7f800000); }

__device__ __forceinline__ void mma16816(float* d, const u32* a, const u32* b) {
    asm volatile("mma.sync.aligned.m16n8k16.row.col.f32.bf16.bf16.f32 "
                 "{%0,%1,%2,%3},{%4,%5,%6,%7},{%8,%9},{%0,%1,%2,%3};"
                 : "+f"(d[0]), "+f"(d[1]), "+f"(d[2]), "+f"(d[3])
                 : "r"(a[0]), "r"(a[1]), "r"(a[2]), "r"(a[3]), "r"(b[0]), "r"(b[1]));
}

__device__ __forceinline__ void split4(const float* __restrict__ src, size_t i,
                                       u16* __restrict__ hi, u16* __restrict__ lo) {
    float4 v = *(const float4*)(src + i);
    float f[4] = {v.x, v.y, v.z, v.w};
    u16 hh[4], ll[4];
#pragma unroll
    for (int j = 0; j < 4; j++) {
        __nv_bfloat16 b = __float2bfloat16(f[j]);
        hh[j] = __bfloat16_as_ushort(b);
        ll[j] = __bfloat16_as_ushort(__float2bfloat16(f[j] - __bfloat162float(b)));
    }
    ushort4 h = {hh[0], hh[1], hh[2], hh[3]}, l = {ll[0], ll[1], ll[2], ll[3]};
    *(ushort4*)(hi + i) = h;
    *(ushort4*)(lo + i) = l;
}

// globals referenced ONLY inside device code (host-side symbol address is invalid!)
__global__ __launch_bounds__(256) void split_hs_kernel(const float* __restrict__ in) {
    size_t i = ((size_t)blockIdx.x * 256 + threadIdx.x) * 4;
    split4(in, i, g_hsHi, g_hsLo);
}
__global__ __launch_bounds__(256) void split_o_kernel() {
    size_t i = ((size_t)blockIdx.x * 256 + threadIdx.x) * 4;
    split4(g_o, i, g_oHi, g_oLo);
}

// ---- split + transpose weights W[k][n] -> WT[n][k] ----
__global__ __launch_bounds__(256) void splitT_kernel(const float* __restrict__ W0,
                                                     const float* __restrict__ W1,
                                                     const float* __restrict__ W2,
                                                     const float* __restrict__ W3) {
    const float* W = (blockIdx.z == 0) ? W0 : (blockIdx.z == 1) ? W1 : (blockIdx.z == 2) ? W2 : W3;
    u16* oh = g_WTHi[blockIdx.z];
    u16* ol = g_WTLo[blockIdx.z];
    __shared__ float t[32][33];
    const int tx = threadIdx.x & 31, ty = threadIdx.x >> 5;
    const int n0 = blockIdx.x * 32, k0 = blockIdx.y * 32;
    for (int r = ty; r < 32; r += 8)
        t[r][tx] = W[(size_t)(k0 + r) * HIDN + n0 + tx];
    __syncthreads();
    for (int r = ty; r < 32; r += 8) {
        float v = t[tx][r];
        __nv_bfloat16 h = __float2bfloat16(v);
        __nv_bfloat16 l = __float2bfloat16(v - __bfloat162float(h));
        size_t o = (size_t)(n0 + r) * HIDN + k0 + tx;
        oh[o] = __bfloat16_as_ushort(h);
        ol[o] = __bfloat16_as_ushort(l);
    }
}

// ============================================================
// bf16-split GEMM via mma.sync: C[M][N] = A[M][K] @ WT[N][K]^T
// 128x128 tile, BK=32, 8 warps (4m x 2n), warp tile 32x64.
// uint4 staging: each thread copies 16 contiguous bf16 per buffer.
// ============================================================
__device__ __forceinline__ void mma_gemm_body(const u16* __restrict__ Ah,
                                              const u16* __restrict__ Al,
                                              const u16* __restrict__ Bh,
                                              const u16* __restrict__ Bl,
                                              float* __restrict__ C) {
    __shared__ u16 sAh[128 * SSTR], sAl[128 * SSTR], sBh[128 * SSTR], sBl[128 * SSTR];

    const int tid = threadIdx.x, lane = tid & 31, warp = tid >> 5;
    const int wm = (warp & 3) * 32, wn = (warp >> 2) * 64;
    const int cRow = blockIdx.y << 7, cCol = blockIdx.x << 7;
    const int lrow = tid >> 1, lhalf = (tid & 1) << 4;

    float acc[2][8][4];
#pragma unroll
    for (int mt = 0; mt < 2; mt++)
#pragma unroll
        for (int nt = 0; nt < 8; nt++)
#pragma unroll
            for (int j = 0; j < 4; j++) acc[mt][nt][j] = 0.f;

    const int qrow = lane >> 2, qcol = (lane & 3) << 1;

    for (int k0 = 0; k0 < HIDN; k0 += 32) {
        const size_t ga = (size_t)(cRow + lrow) * HIDN + k0 + lhalf;
        const size_t gb = (size_t)(cCol + lrow) * HIDN + k0 + lhalf;
        // uint4 = 8 bf16; two per buffer covers the full 16-element span
        uint4 va0 = *(const uint4*)(Ah + ga), va1 = *(const uint4*)(Ah + ga + 8);
        uint4 vb0 = *(const uint4*)(Al + ga), vb1 = *(const uint4*)(Al + ga + 8);
        uint4 vc0 = *(const uint4*)(Bh + gb), vc1 = *(const uint4*)(Bh + gb + 8);
        uint4 vd0 = *(const uint4*)(Bl + gb), vd1 = *(const uint4*)(Bl + gb + 8);
        __syncthreads();
        const int so = lrow * SSTR + lhalf;
        *(uint4*)(sAh + so) = va0; *(uint4*)(sAh + so + 8) = va1;
        *(uint4*)(sAl + so) = vb0; *(uint4*)(sAl + so + 8) = vb1;
        *(uint4*)(sBh + so) = vc0; *(uint4*)(sBh + so + 8) = vc1;
        *(uint4*)(sBl + so) = vd0; *(uint4*)(sBl + so + 8) = vd1;
        __syncthreads();

#pragma unroll
        for (int kk = 0; kk < 32; kk += 16) {
            u32 ah[2][4], al[2][4];
#pragma unroll
            for (int mt = 0; mt < 2; mt++) {
                const int base = (wm + mt * 16 + qrow) * SSTR + kk + qcol;
                ah[mt][0] = *(const u32*)(sAh + base);
                ah[mt][1] = *(const u32*)(sAh + base + 8 * SSTR);
                ah[mt][2] = *(const u32*)(sAh + base + 8);
                ah[mt][3] = *(const u32*)(sAh + base + 8 * SSTR + 8);
                al[mt][0] = *(const u32*)(sAl + base);
                al[mt][1] = *(const u32*)(sAl + base + 8 * SSTR);
                al[mt][2] = *(const u32*)(sAl + base + 8);
                al[mt][3] = *(const u32*)(sAl + base + 8 * SSTR + 8);
            }
#pragma unroll
            for (int nt = 0; nt < 8; nt++) {
                const int base = (wn + nt * 8 + qrow) * SSTR + kk + qcol;
                u32 bh[2], bl[2];
                bh[0] = *(const u32*)(sBh + base);
                bh[1] = *(const u32*)(sBh + base + 8);
                bl[0] = *(const u32*)(sBl + base);
                bl[1] = *(const u32*)(sBl + base + 8);
#pragma unroll
                for (int mt = 0; mt < 2; mt++) {
                    mma16816(acc[mt][nt], ah[mt], bh);
                    mma16816(acc[mt][nt], al[mt], bh);
                    mma16816(acc[mt][nt], ah[mt], bl);
                }
            }
        }
    }

#pragma unroll
    for (int mt = 0; mt < 2; mt++)
#pragma unroll
        for (int nt = 0; nt < 8; nt++) {
            const int r0 = cRow + wm + mt * 16 + qrow;
            const int c0 = cCol + wn + nt * 8 + qcol;
            float2 lo = {acc[mt][nt][0], acc[mt][nt][1]};
            float2 hi = {acc[mt][nt][2], acc[mt][nt][3]};
            *(float2*)(C + (size_t)r0 * HIDN + c0) = lo;
            *(float2*)(C + (size_t)(r0 + 8) * HIDN + c0) = hi;
        }
}

__global__ __launch_bounds__(256) void gemm_qkv_kernel() {
    float* C = (blockIdx.z == 0) ? g_q : (blockIdx.z == 1) ? g_k : g_v;
    mma_gemm_body(g_hsHi, g_hsLo, g_WTHi[blockIdx.z], g_WTLo[blockIdx.z], C);
}
__global__ __launch_bounds__(256) void gemm_out_kernel(float* __restrict__ out) {
    mma_gemm_body(g_oHi, g_oLo, g_WTHi[3], g_WTLo[3], out);
}

// ---- kg mean ----
__global__ void kgmean_kernel() {
    const int n = blockIdx.x;
    for (int c = threadIdx.x; c < HIDN; c += blockDim.x) {
        float sum = 0.f;
#pragma unroll
        for (int t = 0; t < BLK; t++) sum += g_k[(size_t)(n * BLK + t) * HIDN + c];
        g_kg[n * HIDN + c] = sum * (1.0f / 64.0f);
    }
}

// ---- gate + top-8 (warp per row; lane = block idx) ----
__global__ __launch_bounds__(256) void gate_topk_kernel() {
    __shared__ float kgs[NBLK * 129];
    const int h = blockIdx.y, s0 = blockIdx.x * 32, tid = threadIdx.x;
    for (int i = tid; i < NBLK * HD; i += 256) {
        int n = i >> 7, d = i & 127;
        kgs[n * 129 + d] = g_kg[n * HIDN + h * HD + d];
    }
    __syncthreads();
    const int warp = tid >> 5, lane = tid & 31;
    for (int r = 0; r < 4; r++) {
        const int s = s0 + warp * 4 + r;
        const float* qrow = g_q + (size_t)s * HIDN + h * HD;
        float g = 0.f;
#pragma unroll 8
        for (int d = 0; d < HD; d++) g += __ldg(qrow + d) * kgs[lane * 129 + d];
        const int qb = s >> 6;
        if (lane == qb) g = finf();
        else if (lane > qb) g = -finf();
        unsigned mask = 0;
        float work = g;
#pragma unroll
        for (int it = 0; it < KSEL; it++) {
            float v = work; int idx = lane;
#pragma unroll
            for (int off = 16; off; off >>= 1) {
                float ov = __shfl_xor_sync(0xffffffffu, v, off);
                int   oi = __shfl_xor_sync(0xffffffffu, idx, off);
                if (ov > v || (ov == v && oi < idx)) { v = ov; idx = oi; }
            }
            if (v > -finf()) mask |= (1u << idx);
            if (lane == idx) work = -finf();
        }
        if (lane == 0) g_sel[h * SEQ + s] = mask;
    }
}

// ---- block-sparse attention: CTA (128 thr) per (h, s) ----
__global__ __launch_bounds__(128) void attn_kernel() {
    __shared__ float kb[BLK * 129];
    __shared__ float qs[HD];
    __shared__ float sc[BLK];
    __shared__ float red[2];
    const int h = blockIdx.x >> 11, s = blockIdx.x & (SEQ - 1), tid = threadIdx.x;
    qs[tid] = g_q[(size_t)s * HIDN + h * HD + tid];
    unsigned mask = g_sel[h * SEQ + s];
    const float sm_scale = 0.08838834764831845f;
    float m = -finf(), l = 0.f, acc = 0.f;
    __syncthreads();
    while (mask) {
        const int n = __ffs(mask) - 1;
        mask &= mask - 1;
        const float* kbase = g_k + (size_t)(n * BLK) * HIDN + h * HD + tid;
#pragma unroll 8
        for (int t = 0; t < BLK; t++) kb[t * 129 + tid] = kbase[(size_t)t * HIDN];
        __syncthreads();
        if (tid < BLK) {
            const int kp = n * BLK + tid;
            if (kp <= s) {
                float d0 = 0.f;
#pragma unroll 8
                for (int d = 0; d < HD; d++) d0 += qs[d] * kb[tid * 129 + d];
                sc[tid] = d0 * sm_scale;
            } else sc[tid] = -finf();
        }
        __syncthreads();
        if (tid < 32) {
            float a = fmaxf(sc[tid], sc[tid + 32]);
#pragma unroll
            for (int off = 16; off; off >>= 1) a = fmaxf(a, __shfl_xor_sync(0xffffffffu, a, off));
            if (tid == 0) red[0] = a;
        }
        __syncthreads();
        const float newm = fmaxf(m, red[0]);
        const float alpha = expf(m - newm);
        if (tid < BLK) sc[tid] = expf(sc[tid] - newm);
        __syncthreads();
        if (tid < 32) {
            float a = sc[tid] + sc[tid + 32];
#pragma unroll
            for (int off = 16; off; off >>= 1) a += __shfl_xor_sync(0xffffffffu, a, off);
            if (tid == 0) red[1] = a;
        }
        __syncthreads();
        l = l * alpha + red[1];
        m = newm;
        const float* vbase = g_v + (size_t)(n * BLK) * HIDN + h * HD + tid;
#pragma unroll 8
        for (int t = 0; t < BLK; t++) kb[t * 129 + tid] = vbase[(size_t)t * HIDN];
        __syncthreads();
        acc *= alpha;
#pragma unroll 16
        for (int t = 0; t < BLK; t++) acc += sc[t] * kb[t * 129 + tid];
        __syncthreads();
    }
    g_o[(size_t)s * HIDN + h * HD + tid] = acc / l;
}

extern "C" void kernel_launch(void* const* d_in, const int* in_sizes, int n_in,
                              void* d_out, int out_size) {
    const float* hs = (const float*)d_in[0];
    const float* Wq = (const float*)d_in[1];
    const float* Wk = (const float*)d_in[2];
    const float* Wv = (const float*)d_in[3];
    const float* Wo = (const float*)d_in[4];
    float* out = (float*)d_out;

    split_hs_kernel<<<SEQ * HIDN / 1024, 256>>>(hs);
    dim3 gw(HIDN / 32, HIDN / 32, 4);
    splitT_kernel<<<gw, 256>>>(Wq, Wk, Wv, Wo);

    dim3 gq(HIDN / 128, SEQ / 128, 3);
    gemm_qkv_kernel<<<gq, 256>>>();

    kgmean_kernel<<<NBLK, 256>>>();
    dim3 gg(SEQ / 32, NH);
    gate_topk_kernel<<<gg, 256>>>();
    attn_kernel<<<NH * SEQ, 128>>>();

    split_o_kernel<<<SEQ * HIDN / 1024, 256>>>();
    dim3 go(HIDN / 128, SEQ / 128);
    gemm_out_kernel<<<go, 256>>>(out);
}

// round 8
// speedup vs baseline: 1.5761x; 1.1751x over previous
#include <cuda_runtime.h>
#include <cuda_bf16.h>

typedef unsigned short u16;
typedef unsigned int   u32;

#define SEQ   2048
#define HIDN  2048
#define NH    16
#define HD    128
#define NBLK  32
#define BLK   64
#define KSEL  8
#define SSTR  40   // GEMM smem row stride in bf16 units
#define VPAD  144  // attn K/V row: 4 sub-rows of 36 floats
#define SCP   65   // score row pad

__device__ float    g_q[SEQ * HIDN];
__device__ float    g_k[SEQ * HIDN];
__device__ float    g_v[SEQ * HIDN];
__device__ float    g_kg[NBLK * HIDN];
__device__ unsigned g_sel[NH * SEQ];
__device__ float    g_o[SEQ * HIDN];
__device__ u16 g_hsHi[SEQ * HIDN];
__device__ u16 g_hsLo[SEQ * HIDN];
__device__ u16 g_WTHi[4][HIDN * HIDN];
__device__ u16 g_WTLo[4][HIDN * HIDN];
__device__ u16 g_oHi[SEQ * HIDN];
__device__ u16 g_oLo[SEQ * HIDN];

__device__ __forceinline__ float finf() { return __int_as_float(0x7f800000); }

__device__ __forceinline__ void mma16816(float* d, const u32* a, const u32* b) {
    asm volatile("mma.sync.aligned.m16n8k16.row.col.f32.bf16.bf16.f32 "
                 "{%0,%1,%2,%3},{%4,%5,%6,%7},{%8,%9},{%0,%1,%2,%3};"
                 : "+f"(d[0]), "+f"(d[1]), "+f"(d[2]), "+f"(d[3])
                 : "r"(a[0]), "r"(a[1]), "r"(a[2]), "r"(a[3]), "r"(b[0]), "r"(b[1]));
}

__device__ __forceinline__ void split4(const float* __restrict__ src, size_t i,
                                       u16* __restrict__ hi, u16* __restrict__ lo) {
    float4 v = *(const float4*)(src + i);
    float f[4] = {v.x, v.y, v.z, v.w};
    u16 hh[4], ll[4];
#pragma unroll
    for (int j = 0; j < 4; j++) {
        __nv_bfloat16 b = __float2bfloat16(f[j]);
        hh[j] = __bfloat16_as_ushort(b);
        ll[j] = __bfloat16_as_ushort(__float2bfloat16(f[j] - __bfloat162float(b)));
    }
    ushort4 h = {hh[0], hh[1], hh[2], hh[3]}, l = {ll[0], ll[1], ll[2], ll[3]};
    *(ushort4*)(hi + i) = h;
    *(ushort4*)(lo + i) = l;
}

__global__ __launch_bounds__(256) void split_hs_kernel(const float* __restrict__ in) {
    size_t i = ((size_t)blockIdx.x * 256 + threadIdx.x) * 4;
    split4(in, i, g_hsHi, g_hsLo);
}
__global__ __launch_bounds__(256) void split_o_kernel() {
    size_t i = ((size_t)blockIdx.x * 256 + threadIdx.x) * 4;
    split4(g_o, i, g_oHi, g_oLo);
}

// ---- split + transpose weights W[k][n] -> WT[n][k] ----
__global__ __launch_bounds__(256) void splitT_kernel(const float* __restrict__ W0,
                                                     const float* __restrict__ W1,
                                                     const float* __restrict__ W2,
                                                     const float* __restrict__ W3) {
    const float* W = (blockIdx.z == 0) ? W0 : (blockIdx.z == 1) ? W1 : (blockIdx.z == 2) ? W2 : W3;
    u16* oh = g_WTHi[blockIdx.z];
    u16* ol = g_WTLo[blockIdx.z];
    __shared__ float t[32][33];
    const int tx = threadIdx.x & 31, ty = threadIdx.x >> 5;
    const int n0 = blockIdx.x * 32, k0 = blockIdx.y * 32;
    for (int r = ty; r < 32; r += 8)
        t[r][tx] = W[(size_t)(k0 + r) * HIDN + n0 + tx];
    __syncthreads();
    for (int r = ty; r < 32; r += 8) {
        float v = t[tx][r];
        __nv_bfloat16 h = __float2bfloat16(v);
        __nv_bfloat16 l = __float2bfloat16(v - __bfloat162float(h));
        size_t o = (size_t)(n0 + r) * HIDN + k0 + tx;
        oh[o] = __bfloat16_as_ushort(h);
        ol[o] = __bfloat16_as_ushort(l);
    }
}

// ---- bf16-split GEMM via mma.sync (unchanged from R7 pass) ----
__device__ __forceinline__ void mma_gemm_body(const u16* __restrict__ Ah,
                                              const u16* __restrict__ Al,
                                              const u16* __restrict__ Bh,
                                              const u16* __restrict__ Bl,
                                              float* __restrict__ C) {
    __shared__ u16 sAh[128 * SSTR], sAl[128 * SSTR], sBh[128 * SSTR], sBl[128 * SSTR];

    const int tid = threadIdx.x, lane = tid & 31, warp = tid >> 5;
    const int wm = (warp & 3) * 32, wn = (warp >> 2) * 64;
    const int cRow = blockIdx.y << 7, cCol = blockIdx.x << 7;
    const int lrow = tid >> 1, lhalf = (tid & 1) << 4;

    float acc[2][8][4];
#pragma unroll
    for (int mt = 0; mt < 2; mt++)
#pragma unroll
        for (int nt = 0; nt < 8; nt++)
#pragma unroll
            for (int j = 0; j < 4; j++) acc[mt][nt][j] = 0.f;

    const int qrow = lane >> 2, qcol = (lane & 3) << 1;

    for (int k0 = 0; k0 < HIDN; k0 += 32) {
        const size_t ga = (size_t)(cRow + lrow) * HIDN + k0 + lhalf;
        const size_t gb = (size_t)(cCol + lrow) * HIDN + k0 + lhalf;
        uint4 va0 = *(const uint4*)(Ah + ga), va1 = *(const uint4*)(Ah + ga + 8);
        uint4 vb0 = *(const uint4*)(Al + ga), vb1 = *(const uint4*)(Al + ga + 8);
        uint4 vc0 = *(const uint4*)(Bh + gb), vc1 = *(const uint4*)(Bh + gb + 8);
        uint4 vd0 = *(const uint4*)(Bl + gb), vd1 = *(const uint4*)(Bl + gb + 8);
        __syncthreads();
        const int so = lrow * SSTR + lhalf;
        *(uint4*)(sAh + so) = va0; *(uint4*)(sAh + so + 8) = va1;
        *(uint4*)(sAl + so) = vb0; *(uint4*)(sAl + so + 8) = vb1;
        *(uint4*)(sBh + so) = vc0; *(uint4*)(sBh + so + 8) = vc1;
        *(uint4*)(sBl + so) = vd0; *(uint4*)(sBl + so + 8) = vd1;
        __syncthreads();

#pragma unroll
        for (int kk = 0; kk < 32; kk += 16) {
            u32 ah[2][4], al[2][4];
#pragma unroll
            for (int mt = 0; mt < 2; mt++) {
                const int base = (wm + mt * 16 + qrow) * SSTR + kk + qcol;
                ah[mt][0] = *(const u32*)(sAh + base);
                ah[mt][1] = *(const u32*)(sAh + base + 8 * SSTR);
                ah[mt][2] = *(const u32*)(sAh + base + 8);
                ah[mt][3] = *(const u32*)(sAh + base + 8 * SSTR + 8);
                al[mt][0] = *(const u32*)(sAl + base);
                al[mt][1] = *(const u32*)(sAl + base + 8 * SSTR);
                al[mt][2] = *(const u32*)(sAl + base + 8);
                al[mt][3] = *(const u32*)(sAl + base + 8 * SSTR + 8);
            }
#pragma unroll
            for (int nt = 0; nt < 8; nt++) {
                const int base = (wn + nt * 8 + qrow) * SSTR + kk + qcol;
                u32 bh[2], bl[2];
                bh[0] = *(const u32*)(sBh + base);
                bh[1] = *(const u32*)(sBh + base + 8);
                bl[0] = *(const u32*)(sBl + base);
                bl[1] = *(const u32*)(sBl + base + 8);
#pragma unroll
                for (int mt = 0; mt < 2; mt++) {
                    mma16816(acc[mt][nt], ah[mt], bh);
                    mma16816(acc[mt][nt], al[mt], bh);
                    mma16816(acc[mt][nt], ah[mt], bl);
                }
            }
        }
    }

#pragma unroll
    for (int mt = 0; mt < 2; mt++)
#pragma unroll
        for (int nt = 0; nt < 8; nt++) {
            const int r0 = cRow + wm + mt * 16 + qrow;
            const int c0 = cCol + wn + nt * 8 + qcol;
            float2 lo = {acc[mt][nt][0], acc[mt][nt][1]};
            float2 hi = {acc[mt][nt][2], acc[mt][nt][3]};
            *(float2*)(C + (size_t)r0 * HIDN + c0) = lo;
            *(float2*)(C + (size_t)(r0 + 8) * HIDN + c0) = hi;
        }
}

__global__ __launch_bounds__(256) void gemm_qkv_kernel() {
    float* C = (blockIdx.z == 0) ? g_q : (blockIdx.z == 1) ? g_k : g_v;
    mma_gemm_body(g_hsHi, g_hsLo, g_WTHi[blockIdx.z], g_WTLo[blockIdx.z], C);
}
__global__ __launch_bounds__(256) void gemm_out_kernel(float* __restrict__ out) {
    mma_gemm_body(g_oHi, g_oLo, g_WTHi[3], g_WTLo[3], out);
}

// ---- kg mean (widened grid) ----
__global__ void kgmean_kernel() {
    const int n = blockIdx.x;
    const int c = blockIdx.y * 256 + threadIdx.x;
    float sum = 0.f;
#pragma unroll
    for (int t = 0; t < BLK; t++) sum += g_k[(size_t)(n * BLK + t) * HIDN + c];
    g_kg[n * HIDN + c] = sum * (1.0f / 64.0f);
}

// ---- gate + top-8 (unchanged) ----
__global__ __launch_bounds__(256) void gate_topk_kernel() {
    __shared__ float kgs[NBLK * 129];
    const int h = blockIdx.y, s0 = blockIdx.x * 32, tid = threadIdx.x;
    for (int i = tid; i < NBLK * HD; i += 256) {
        int n = i >> 7, d = i & 127;
        kgs[n * 129 + d] = g_kg[n * HIDN + h * HD + d];
    }
    __syncthreads();
    const int warp = tid >> 5, lane = tid & 31;
    for (int r = 0; r < 4; r++) {
        const int s = s0 + warp * 4 + r;
        const float* qrow = g_q + (size_t)s * HIDN + h * HD;
        float g = 0.f;
#pragma unroll 8
        for (int d = 0; d < HD; d++) g += __ldg(qrow + d) * kgs[lane * 129 + d];
        const int qb = s >> 6;
        if (lane == qb) g = finf();
        else if (lane > qb) g = -finf();
        unsigned mask = 0;
        float work = g;
#pragma unroll
        for (int it = 0; it < KSEL; it++) {
            float v = work; int idx = lane;
#pragma unroll
            for (int off = 16; off; off >>= 1) {
                float ov = __shfl_xor_sync(0xffffffffu, v, off);
                int   oi = __shfl_xor_sync(0xffffffffu, idx, off);
                if (ov > v || (ov == v && oi < idx)) { v = ov; idx = oi; }
            }
            if (v > -finf()) mask |= (1u << idx);
            if (lane == idx) work = -finf();
        }
        if (lane == 0) g_sel[h * SEQ + s] = mask;
    }
}

// ============================================================
// Query-block-tiled block-sparse attention.
// CTA = (qblock, head): 64 queries, 256 threads, quad (4 thr) per query.
// K/V union blocks loaded to smem once per 64 queries.
// ============================================================
__global__ __launch_bounds__(256, 2) void attn2_kernel() {
    extern __shared__ float dyn[];
    float* kb = dyn;                 // [64][VPAD]
    float* vb = dyn + 64 * VPAD;     // [64][VPAD]
    float* sc = dyn + 128 * VPAD;    // [64][SCP]
    __shared__ unsigned selm[64];
    __shared__ unsigned s_uni;

    const int qb = blockIdx.x, h = blockIdx.y;
    const int tid = threadIdx.x, qi = tid >> 2, j = tid & 3;
    const int s = qb * BLK + qi;
    const unsigned qmask = 0xFu << ((tid & 31) & ~3);
    const float sm_scale = 0.08838834764831845f;

    if (tid < 64) selm[tid] = g_sel[h * SEQ + qb * BLK + tid];
    __syncthreads();
    if (tid == 0) {
        unsigned u = 0;
#pragma unroll
        for (int i = 0; i < 64; i++) u |= selm[i];
        s_uni = u;
    }

    // q row into registers: thread owns dims [j*32, j*32+32)
    float qreg[32];
    {
        const float4* qp = (const float4*)(g_q + (size_t)s * HIDN + h * HD + j * 32);
#pragma unroll
        for (int i = 0; i < 8; i++) {
            float4 t4 = qp[i];
            qreg[4 * i] = t4.x; qreg[4 * i + 1] = t4.y;
            qreg[4 * i + 2] = t4.z; qreg[4 * i + 3] = t4.w;
        }
    }
    __syncthreads();
    unsigned uni = s_uni;
    const unsigned mysel = selm[qi];

    float m = -finf(), l = 0.f, acc[32];
#pragma unroll
    for (int i = 0; i < 32; i++) acc[i] = 0.f;

    while (uni) {
        const int n = __ffs(uni) - 1;
        uni &= uni - 1;

        // cooperative K+V load: 64 rows x 128 floats each, sub-row padded layout
        for (int x = tid; x < 2048; x += 256) {
            const int r = x >> 5, d = (x & 31) << 2;
            const size_t g = (size_t)(n * BLK + r) * HIDN + h * HD + d;
            const int dst = r * VPAD + (d >> 5) * 36 + (d & 31);
            *(float4*)(kb + dst) = *(const float4*)(g_k + g);
            *(float4*)(vb + dst) = *(const float4*)(g_v + g);
        }
        __syncthreads();

        if ((mysel >> n) & 1) {
            // --- scores: quad-partial dots + butterfly reduce ---
            float smax = -finf();
            const int kcaus = (n == qb) ? qi : 63;
            for (int k = 0; k < 64; k++) {
                const float* kp = kb + k * VPAD + j * 36;
                float p0 = 0.f, p1 = 0.f, p2 = 0.f, p3 = 0.f;
#pragma unroll
                for (int i = 0; i < 32; i += 4) {
                    p0 += qreg[i] * kp[i];
                    p1 += qreg[i + 1] * kp[i + 1];
                    p2 += qreg[i + 2] * kp[i + 2];
                    p3 += qreg[i + 3] * kp[i + 3];
                }
                float p = (p0 + p1) + (p2 + p3);
                p += __shfl_xor_sync(qmask, p, 1);
                p += __shfl_xor_sync(qmask, p, 2);
                const float scv = (k <= kcaus) ? p * sm_scale : -finf();
                if ((k & 3) == j) sc[qi * SCP + k] = scv;
                smax = fmaxf(smax, scv);
            }
            __syncwarp(qmask);

            const float newm = fmaxf(m, smax);
            const float alpha = __expf(m - newm);
            m = newm;
            l *= alpha;
#pragma unroll
            for (int i = 0; i < 32; i++) acc[i] *= alpha;

            // --- p pass: my 16 keys ---
            float lsum = 0.f;
#pragma unroll
            for (int kk = 0; kk < 16; kk++) {
                const int k = (kk << 2) | j;
                const float p = __expf(sc[qi * SCP + k] - m);
                sc[qi * SCP + k] = p;
                lsum += p;
            }
            lsum += __shfl_xor_sync(qmask, lsum, 1);
            lsum += __shfl_xor_sync(qmask, lsum, 2);
            l += lsum;
            __syncwarp(qmask);

            // --- PV: thread owns dims [j*32, j*32+32) ---
            for (int k = 0; k < 64; k++) {
                const float p = sc[qi * SCP + k];
                const float* vp = vb + k * VPAD + j * 36;
#pragma unroll
                for (int i = 0; i < 32; i++) acc[i] += p * vp[i];
            }
        }
        __syncthreads();   // protect kb/vb before next block
    }

    const float inv = 1.f / l;
    float4* op = (float4*)(g_o + (size_t)s * HIDN + h * HD + j * 32);
#pragma unroll
    for (int i = 0; i < 8; i++) {
        float4 t4 = {acc[4 * i] * inv, acc[4 * i + 1] * inv,
                     acc[4 * i + 2] * inv, acc[4 * i + 3] * inv};
        op[i] = t4;
    }
}

#define ATTN_SMEM ((128 * VPAD + 64 * SCP) * 4)

extern "C" void kernel_launch(void* const* d_in, const int* in_sizes, int n_in,
                              void* d_out, int out_size) {
    const float* hs = (const float*)d_in[0];
    const float* Wq = (const float*)d_in[1];
    const float* Wk = (const float*)d_in[2];
    const float* Wv = (const float*)d_in[3];
    const float* Wo = (const float*)d_in[4];
    float* out = (float*)d_out;

    cudaFuncSetAttribute(attn2_kernel, cudaFuncAttributeMaxDynamicSharedMemorySize, ATTN_SMEM);

    split_hs_kernel<<<SEQ * HIDN / 1024, 256>>>(hs);
    dim3 gw(HIDN / 32, HIDN / 32, 4);
    splitT_kernel<<<gw, 256>>>(Wq, Wk, Wv, Wo);

    dim3 gq(HIDN / 128, SEQ / 128, 3);
    gemm_qkv_kernel<<<gq, 256>>>();

    dim3 gk(NBLK, HIDN / 256);
    kgmean_kernel<<<gk, 256>>>();
    dim3 gg(SEQ / 32, NH);
    gate_topk_kernel<<<gg, 256>>>();

    dim3 ga(NBLK, NH);
    attn2_kernel<<<ga, 256, ATTN_SMEM>>>();

    split_o_kernel<<<SEQ * HIDN / 1024, 256>>>();
    dim3 go(HIDN / 128, SEQ / 128);
    gemm_out_kernel<<<go, 256>>>(out);
}

// round 9
// speedup vs baseline: 1.5994x; 1.0148x over previous
#include <cuda_runtime.h>
#include <cuda_bf16.h>

typedef unsigned short u16;
typedef unsigned int   u32;

#define SEQ   2048
#define HIDN  2048
#define NH    16
#define HD    128
#define NBLK  32
#define BLK   64
#define KSEL  8
#define SSTR  40   // GEMM smem row stride in bf16 units
#define VPAD  144  // attn K/V row: 4 sub-rows of 36 floats
#define SCP   65   // score row pad

#define STAGE_B 40960            // bytes per pipeline stage (4 bufs x 128 x SSTR x 2B)
#define GEMM_SMEM (2 * STAGE_B)  // 80 KB dynamic

__device__ float    g_q[SEQ * HIDN];
__device__ float    g_k[SEQ * HIDN];
__device__ float    g_v[SEQ * HIDN];
__device__ float    g_kg[NBLK * HIDN];
__device__ unsigned g_sel[NH * SEQ];
__device__ float    g_o[SEQ * HIDN];
__device__ u16 g_hsHi[SEQ * HIDN];
__device__ u16 g_hsLo[SEQ * HIDN];
__device__ u16 g_WTHi[4][HIDN * HIDN];
__device__ u16 g_WTLo[4][HIDN * HIDN];
__device__ u16 g_oHi[SEQ * HIDN];
__device__ u16 g_oLo[SEQ * HIDN];

__device__ __forceinline__ float finf() { return __int_as_float(0x7f800000); }

__device__ __forceinline__ u32 cvta_s(const void* p) {
    u32 a;
    asm("{ .reg .u64 t; cvta.to.shared.u64 t, %1; cvt.u32.u64 %0, t; }" : "=r"(a) : "l"(p));
    return a;
}
__device__ __forceinline__ void cpa16(u32 dst, const void* src) {
    asm volatile("cp.async.cg.shared.global [%0], [%1], 16;" :: "r"(dst), "l"(src));
}
__device__ __forceinline__ void cpa_commit() {
    asm volatile("cp.async.commit_group;" ::: "memory");
}
__device__ __forceinline__ void cpa_wait1() {
    asm volatile("cp.async.wait_group 1;" ::: "memory");
}
__device__ __forceinline__ void cpa_wait0() {
    asm volatile("cp.async.wait_group 0;" ::: "memory");
}

__device__ __forceinline__ void mma16816(float* d, const u32* a, const u32* b) {
    asm volatile("mma.sync.aligned.m16n8k16.row.col.f32.bf16.bf16.f32 "
                 "{%0,%1,%2,%3},{%4,%5,%6,%7},{%8,%9},{%0,%1,%2,%3};"
                 : "+f"(d[0]), "+f"(d[1]), "+f"(d[2]), "+f"(d[3])
                 : "r"(a[0]), "r"(a[1]), "r"(a[2]), "r"(a[3]), "r"(b[0]), "r"(b[1]));
}

__device__ __forceinline__ void split4(const float* __restrict__ src, size_t i,
                                       u16* __restrict__ hi, u16* __restrict__ lo) {
    float4 v = *(const float4*)(src + i);
    float f[4] = {v.x, v.y, v.z, v.w};
    u16 hh[4], ll[4];
#pragma unroll
    for (int j = 0; j < 4; j++) {
        __nv_bfloat16 b = __float2bfloat16(f[j]);
        hh[j] = __bfloat16_as_ushort(b);
        ll[j] = __bfloat16_as_ushort(__float2bfloat16(f[j] - __bfloat162float(b)));
    }
    ushort4 h = {hh[0], hh[1], hh[2], hh[3]}, l = {ll[0], ll[1], ll[2], ll[3]};
    *(ushort4*)(hi + i) = h;
    *(ushort4*)(lo + i) = l;
}

__global__ __launch_bounds__(256) void split_hs_kernel(const float* __restrict__ in) {
    size_t i = ((size_t)blockIdx.x * 256 + threadIdx.x) * 4;
    split4(in, i, g_hsHi, g_hsLo);
}
__global__ __launch_bounds__(256) void split_o_kernel() {
    size_t i = ((size_t)blockIdx.x * 256 + threadIdx.x) * 4;
    split4(g_o, i, g_oHi, g_oLo);
}

// ---- split + transpose weights W[k][n] -> WT[n][k] ----
__global__ __launch_bounds__(256) void splitT_kernel(const float* __restrict__ W0,
                                                     const float* __restrict__ W1,
                                                     const float* __restrict__ W2,
                                                     const float* __restrict__ W3) {
    const float* W = (blockIdx.z == 0) ? W0 : (blockIdx.z == 1) ? W1 : (blockIdx.z == 2) ? W2 : W3;
    u16* oh = g_WTHi[blockIdx.z];
    u16* ol = g_WTLo[blockIdx.z];
    __shared__ float t[32][33];
    const int tx = threadIdx.x & 31, ty = threadIdx.x >> 5;
    const int n0 = blockIdx.x * 32, k0 = blockIdx.y * 32;
    for (int r = ty; r < 32; r += 8)
        t[r][tx] = W[(size_t)(k0 + r) * HIDN + n0 + tx];
    __syncthreads();
    for (int r = ty; r < 32; r += 8) {
        float v = t[tx][r];
        __nv_bfloat16 h = __float2bfloat16(v);
        __nv_bfloat16 l = __float2bfloat16(v - __bfloat162float(h));
        size_t o = (size_t)(n0 + r) * HIDN + k0 + tx;
        oh[o] = __bfloat16_as_ushort(h);
        ol[o] = __bfloat16_as_ushort(l);
    }
}

// ============================================================
// bf16-split GEMM, cp.async double-buffered (2-stage), BK=32.
// ============================================================
__device__ __forceinline__ void mma_gemm_body(const u16* __restrict__ Ah,
                                              const u16* __restrict__ Al,
                                              const u16* __restrict__ Bh,
                                              const u16* __restrict__ Bl,
                                              float* __restrict__ C) {
    extern __shared__ u16 dynsm[];

    const int tid = threadIdx.x, lane = tid & 31, warp = tid >> 5;
    const int wm = (warp & 3) * 32, wn = (warp >> 2) * 64;
    const int cRow = blockIdx.y << 7, cCol = blockIdx.x << 7;
    const int lrow = tid >> 1, lhalf = (tid & 1) << 4;

    const u32 sbase = cvta_s(dynsm);
    const u32 so = (u32)(lrow * SSTR + lhalf) * 2;   // byte offset within a buffer

    // issue one stage of loads (stage st, k-tile kt)
    auto issue = [&](int kt, int st) {
        const size_t ga = (size_t)(cRow + lrow) * HIDN + (kt << 5) + lhalf;
        const size_t gb = (size_t)(cCol + lrow) * HIDN + (kt << 5) + lhalf;
        const u32 s0 = sbase + st * STAGE_B + so;
        cpa16(s0,             Ah + ga); cpa16(s0 + 16,             Ah + ga + 8);
        cpa16(s0 + 10240,     Al + ga); cpa16(s0 + 10240 + 16,     Al + ga + 8);
        cpa16(s0 + 20480,     Bh + gb); cpa16(s0 + 20480 + 16,     Bh + gb + 8);
        cpa16(s0 + 30720,     Bl + gb); cpa16(s0 + 30720 + 16,     Bl + gb + 8);
        cpa_commit();
    };

    float acc[2][8][4];
#pragma unroll
    for (int mt = 0; mt < 2; mt++)
#pragma unroll
        for (int nt = 0; nt < 8; nt++)
#pragma unroll
            for (int j = 0; j < 4; j++) acc[mt][nt][j] = 0.f;

    const int qrow = lane >> 2, qcol = (lane & 3) << 1;

    issue(0, 0);

    for (int kt = 0; kt < 64; kt++) {
        if (kt + 1 < 64) { issue(kt + 1, (kt + 1) & 1); cpa_wait1(); }
        else             { cpa_wait0(); }
        __syncthreads();

        const u16* sAh = dynsm + (size_t)(kt & 1) * (STAGE_B / 2);
        const u16* sAl = sAh + 5120;
        const u16* sBh = sAh + 10240;
        const u16* sBl = sAh + 15360;

#pragma unroll
        for (int kk = 0; kk < 32; kk += 16) {
            u32 ah[2][4], al[2][4];
#pragma unroll
            for (int mt = 0; mt < 2; mt++) {
                const int base = (wm + mt * 16 + qrow) * SSTR + kk + qcol;
                ah[mt][0] = *(const u32*)(sAh + base);
                ah[mt][1] = *(const u32*)(sAh + base + 8 * SSTR);
                ah[mt][2] = *(const u32*)(sAh + base + 8);
                ah[mt][3] = *(const u32*)(sAh + base + 8 * SSTR + 8);
                al[mt][0] = *(const u32*)(sAl + base);
                al[mt][1] = *(const u32*)(sAl + base + 8 * SSTR);
                al[mt][2] = *(const u32*)(sAl + base + 8);
                al[mt][3] = *(const u32*)(sAl + base + 8 * SSTR + 8);
            }
#pragma unroll
            for (int nt = 0; nt < 8; nt++) {
                const int base = (wn + nt * 8 + qrow) * SSTR + kk + qcol;
                u32 bh[2], bl[2];
                bh[0] = *(const u32*)(sBh + base);
                bh[1] = *(const u32*)(sBh + base + 8);
                bl[0] = *(const u32*)(sBl + base);
                bl[1] = *(const u32*)(sBl + base + 8);
#pragma unroll
                for (int mt = 0; mt < 2; mt++) {
                    mma16816(acc[mt][nt], ah[mt], bh);
                    mma16816(acc[mt][nt], al[mt], bh);
                    mma16816(acc[mt][nt], ah[mt], bl);
                }
            }
        }
        __syncthreads();   // all warps done with this stage before it is refilled
    }

#pragma unroll
    for (int mt = 0; mt < 2; mt++)
#pragma unroll
        for (int nt = 0; nt < 8; nt++) {
            const int r0 = cRow + wm + mt * 16 + qrow;
            const int c0 = cCol + wn + nt * 8 + qcol;
            float2 lo = {acc[mt][nt][0], acc[mt][nt][1]};
            float2 hi = {acc[mt][nt][2], acc[mt][nt][3]};
            *(float2*)(C + (size_t)r0 * HIDN + c0) = lo;
            *(float2*)(C + (size_t)(r0 + 8) * HIDN + c0) = hi;
        }
}

__global__ __launch_bounds__(256) void gemm_qkv_kernel() {
    float* C = (blockIdx.z == 0) ? g_q : (blockIdx.z == 1) ? g_k : g_v;
    mma_gemm_body(g_hsHi, g_hsLo, g_WTHi[blockIdx.z], g_WTLo[blockIdx.z], C);
}
__global__ __launch_bounds__(256) void gemm_out_kernel(float* __restrict__ out) {
    mma_gemm_body(g_oHi, g_oLo, g_WTHi[3], g_WTLo[3], out);
}

// ---- kg mean ----
__global__ void kgmean_kernel() {
    const int n = blockIdx.x;
    const int c = blockIdx.y * 256 + threadIdx.x;
    float sum = 0.f;
#pragma unroll
    for (int t = 0; t < BLK; t++) sum += g_k[(size_t)(n * BLK + t) * HIDN + c];
    g_kg[n * HIDN + c] = sum * (1.0f / 64.0f);
}

// ---- gate + top-8 ----
__global__ __launch_bounds__(256) void gate_topk_kernel() {
    __shared__ float kgs[NBLK * 129];
    const int h = blockIdx.y, s0 = blockIdx.x * 32, tid = threadIdx.x;
    for (int i = tid; i < NBLK * HD; i += 256) {
        int n = i >> 7, d = i & 127;
        kgs[n * 129 + d] = g_kg[n * HIDN + h * HD + d];
    }
    __syncthreads();
    const int warp = tid >> 5, lane = tid & 31;
    for (int r = 0; r < 4; r++) {
        const int s = s0 + warp * 4 + r;
        const float* qrow = g_q + (size_t)s * HIDN + h * HD;
        float g = 0.f;
#pragma unroll 8
        for (int d = 0; d < HD; d++) g += __ldg(qrow + d) * kgs[lane * 129 + d];
        const int qb = s >> 6;
        if (lane == qb) g = finf();
        else if (lane > qb) g = -finf();
        unsigned mask = 0;
        float work = g;
#pragma unroll
        for (int it = 0; it < KSEL; it++) {
            float v = work; int idx = lane;
#pragma unroll
            for (int off = 16; off; off >>= 1) {
                float ov = __shfl_xor_sync(0xffffffffu, v, off);
                int   oi = __shfl_xor_sync(0xffffffffu, idx, off);
                if (ov > v || (ov == v && oi < idx)) { v = ov; idx = oi; }
            }
            if (v > -finf()) mask |= (1u << idx);
            if (lane == idx) work = -finf();
        }
        if (lane == 0) g_sel[h * SEQ + s] = mask;
    }
}

// ---- query-block-tiled block-sparse attention (unchanged from R8 pass) ----
__global__ __launch_bounds__(256, 2) void attn2_kernel() {
    extern __shared__ float dyn[];
    float* kb = dyn;
    float* vb = dyn + 64 * VPAD;
    float* sc = dyn + 128 * VPAD;
    __shared__ unsigned selm[64];
    __shared__ unsigned s_uni;

    const int qb = blockIdx.x, h = blockIdx.y;
    const int tid = threadIdx.x, qi = tid >> 2, j = tid & 3;
    const int s = qb * BLK + qi;
    const unsigned qmask = 0xFu << ((tid & 31) & ~3);
    const float sm_scale = 0.08838834764831845f;

    if (tid < 64) selm[tid] = g_sel[h * SEQ + qb * BLK + tid];
    __syncthreads();
    if (tid == 0) {
        unsigned u = 0;
#pragma unroll
        for (int i = 0; i < 64; i++) u |= selm[i];
        s_uni = u;
    }

    float qreg[32];
    {
        const float4* qp = (const float4*)(g_q + (size_t)s * HIDN + h * HD + j * 32);
#pragma unroll
        for (int i = 0; i < 8; i++) {
            float4 t4 = qp[i];
            qreg[4 * i] = t4.x; qreg[4 * i + 1] = t4.y;
            qreg[4 * i + 2] = t4.z; qreg[4 * i + 3] = t4.w;
        }
    }
    __syncthreads();
    unsigned uni = s_uni;
    const unsigned mysel = selm[qi];

    float m = -finf(), l = 0.f, acc[32];
#pragma unroll
    for (int i = 0; i < 32; i++) acc[i] = 0.f;

    while (uni) {
        const int n = __ffs(uni) - 1;
        uni &= uni - 1;

        for (int x = tid; x < 2048; x += 256) {
            const int r = x >> 5, d = (x & 31) << 2;
            const size_t g = (size_t)(n * BLK + r) * HIDN + h * HD + d;
            const int dst = r * VPAD + (d >> 5) * 36 + (d & 31);
            *(float4*)(kb + dst) = *(const float4*)(g_k + g);
            *(float4*)(vb + dst) = *(const float4*)(g_v + g);
        }
        __syncthreads();

        if ((mysel >> n) & 1) {
            float smax = -finf();
            const int kcaus = (n == qb) ? qi : 63;
            for (int k = 0; k < 64; k++) {
                const float* kp = kb + k * VPAD + j * 36;
                float p0 = 0.f, p1 = 0.f, p2 = 0.f, p3 = 0.f;
#pragma unroll
                for (int i = 0; i < 32; i += 4) {
                    p0 += qreg[i] * kp[i];
                    p1 += qreg[i + 1] * kp[i + 1];
                    p2 += qreg[i + 2] * kp[i + 2];
                    p3 += qreg[i + 3] * kp[i + 3];
                }
                float p = (p0 + p1) + (p2 + p3);
                p += __shfl_xor_sync(qmask, p, 1);
                p += __shfl_xor_sync(qmask, p, 2);
                const float scv = (k <= kcaus) ? p * sm_scale : -finf();
                if ((k & 3) == j) sc[qi * SCP + k] = scv;
                smax = fmaxf(smax, scv);
            }
            __syncwarp(qmask);

            const float newm = fmaxf(m, smax);
            const float alpha = __expf(m - newm);
            m = newm;
            l *= alpha;
#pragma unroll
            for (int i = 0; i < 32; i++) acc[i] *= alpha;

            float lsum = 0.f;
#pragma unroll
            for (int kk = 0; kk < 16; kk++) {
                const int k = (kk << 2) | j;
                const float p = __expf(sc[qi * SCP + k] - m);
                sc[qi * SCP + k] = p;
                lsum += p;
            }
            lsum += __shfl_xor_sync(qmask, lsum, 1);
            lsum += __shfl_xor_sync(qmask, lsum, 2);
            l += lsum;
            __syncwarp(qmask);

            for (int k = 0; k < 64; k++) {
                const float p = sc[qi * SCP + k];
                const float* vp = vb + k * VPAD + j * 36;
#pragma unroll
                for (int i = 0; i < 32; i++) acc[i] += p * vp[i];
            }
        }
        __syncthreads();
    }

    const float inv = 1.f / l;
    float4* op = (float4*)(g_o + (size_t)s * HIDN + h * HD + j * 32);
#pragma unroll
    for (int i = 0; i < 8; i++) {
        float4 t4 = {acc[4 * i] * inv, acc[4 * i + 1] * inv,
                     acc[4 * i + 2] * inv, acc[4 * i + 3] * inv};
        op[i] = t4;
    }
}

#define ATTN_SMEM ((128 * VPAD + 64 * SCP) * 4)

extern "C" void kernel_launch(void* const* d_in, const int* in_sizes, int n_in,
                              void* d_out, int out_size) {
    const float* hs = (const float*)d_in[0];
    const float* Wq = (const float*)d_in[1];
    const float* Wk = (const float*)d_in[2];
    const float* Wv = (const float*)d_in[3];
    const float* Wo = (const float*)d_in[4];
    float* out = (float*)d_out;

    cudaFuncSetAttribute(attn2_kernel, cudaFuncAttributeMaxDynamicSharedMemorySize, ATTN_SMEM);
    cudaFuncSetAttribute(gemm_qkv_kernel, cudaFuncAttributeMaxDynamicSharedMemorySize, GEMM_SMEM);
    cudaFuncSetAttribute(gemm_out_kernel, cudaFuncAttributeMaxDynamicSharedMemorySize, GEMM_SMEM);

    split_hs_kernel<<<SEQ * HIDN / 1024, 256>>>(hs);
    dim3 gw(HIDN / 32, HIDN / 32, 4);
    splitT_kernel<<<gw, 256>>>(Wq, Wk, Wv, Wo);

    dim3 gq(HIDN / 128, SEQ / 128, 3);
    gemm_qkv_kernel<<<gq, 256, GEMM_SMEM>>>();

    dim3 gk(NBLK, HIDN / 256);
    kgmean_kernel<<<gk, 256>>>();
    dim3 gg(SEQ / 32, NH);
    gate_topk_kernel<<<gg, 256>>>();

    dim3 ga(NBLK, NH);
    attn2_kernel<<<ga, 256, ATTN_SMEM>>>();

    split_o_kernel<<<SEQ * HIDN / 1024, 256>>>();
    dim3 go(HIDN / 128, SEQ / 128);
    gemm_out_kernel<<<go, 256, GEMM_SMEM>>>(out);
}